// round 14
// baseline (speedup 1.0000x reference)
#include <cuda_runtime.h>
#include <cuda_fp16.h>
#include <cstdint>
#include <cstddef>

// Conv 3x3 s2 p1: x[32,256,64,64] * w[256,256,3,3] -> out[32,256,32,32]
// (crop mask is all-ones: python slice clamping empties every zero segment).
// Implicit GEMM, swapped operands: D[cout][m] = W[cout][k] * X[k][m],
// K re-enumerated k'=(kh*3+kw)*256+cin. FP16 datapath, fp32 accumulate.
// W streams from L1/L2 via ld.global.nc.v4 into a register double-buffer;
// smem carries X only. This round: all 4 ldsm of a stage issued back-to-back
// at stage entry (one latency exposure instead of two) + 5-stage pipeline.
// Tile 128x128x32, 8 warps (64cx32m), 2 CTAs/SM, cout-pairs adjacent in grid.

namespace {
constexpr int NIT = 72;                        // 2304 / 32
constexpr int XROW = 272;                      // bytes per k-row (256 data + 16 pad)
constexpr int X_STAGE_B = 32 * XROW;           // 8704
constexpr int NSTAGE = 5;
constexpr int SMEM_BYTES = NSTAGE * X_STAGE_B; // 43520 (x2 CTAs = 87KB/SM)
}

// xH[b][cin][ihp(65)][kw(3)][32] halves: pre-shifted, parity-deinterleaved,
// fp16-rounded rows; ihp=0 is an all-zero guard row (ih=-1).
__device__ __half xH[51118080];
// wG: A-fragment stream for direct LDG, 8KB per k16 chunk c (144 chunks):
// halfidx = c*4096 + by*2048 + wc*1024 + mi*256 + lane*8 + reg*2 + hf
__device__ __half wG[589824];

__device__ __forceinline__ uint32_t smem_u32(const void* p) {
  uint32_t a;
  asm("{ .reg .u64 t; cvta.to.shared.u64 t, %1; cvt.u32.u64 %0, t; }" : "=r"(a) : "l"(p));
  return a;
}
__device__ __forceinline__ void ldg128nc(uint32_t* r, const void* p) {
  asm("ld.global.nc.v4.b32 {%0,%1,%2,%3}, [%4];"
      : "=r"(r[0]), "=r"(r[1]), "=r"(r[2]), "=r"(r[3]) : "l"(p));
}
__device__ __forceinline__ void ldsm4t(uint32_t* r, uint32_t a) {
  asm volatile("ldmatrix.sync.aligned.m8n8.x4.trans.shared.b16 {%0,%1,%2,%3}, [%4];"
               : "=r"(r[0]), "=r"(r[1]), "=r"(r[2]), "=r"(r[3]) : "r"(a));
}
__device__ __forceinline__ void cpa16(uint32_t dst, const void* src) {
  asm volatile("cp.async.cg.shared.global [%0], [%1], 16;\n" :: "r"(dst), "l"(src));
}
__device__ __forceinline__ void mma16(float* c, const uint32_t* a, uint32_t b0, uint32_t b1) {
  asm volatile(
      "mma.sync.aligned.m16n8k16.row.col.f32.f16.f16.f32 "
      "{%0,%1,%2,%3}, {%4,%5,%6,%7}, {%8,%9}, {%0,%1,%2,%3};"
      : "+f"(c[0]), "+f"(c[1]), "+f"(c[2]), "+f"(c[3])
      : "r"(a[0]), "r"(a[1]), "r"(a[2]), "r"(a[3]), "r"(b0), "r"(b1));
}

// ---- prepasses ----
__global__ void prep_x(const float4* __restrict__ x4) {
  int i = blockIdx.x * 256 + threadIdx.x;      // covers 8388608 float4s
  float4 v = x4[i];
  __half h0 = __float2half_rn(v.x), h1 = __float2half_rn(v.y);
  __half h2 = __float2half_rn(v.z), h3 = __float2half_rn(v.w);
  int e = i << 2;
  int iw0 = e & 63;                            // 0,4,...,60
  int rid = e >> 6;                            // (b*256+cin)*64 + ih
  int bc = rid >> 6, ih = rid & 63;
  __half* base = xH + (size_t)(bc * 65 + ih + 1) * 96;
  int q = iw0 >> 1;                            // even
  // kw=1 plane: even iw; kw=2 plane: odd iw (q even -> 4B aligned)
  *(__half2*)(base + 32 + q) = __halves2half2(h0, h2);
  *(__half2*)(base + 64 + q) = __halves2half2(h1, h3);
  // kw=0 plane: [0, odd shifted right]
  base[q + 1] = h1;
  if (iw0 < 60) base[q + 2] = h3;
  if (iw0 == 0) base[0] = __float2half_rn(0.f);
  // fused guard-row zeroing (ihp=0): ih==0 threads cover 48 u32 per (b,cin)
  if (ih == 0) {
    uint32_t* g = (uint32_t*)(base - 96);      // guard row, 96 halves = 48 u32
    int j = (iw0 >> 2) * 3;                    // 16 threads x 3 u32 = 48
    g[j] = 0u; g[j + 1] = 0u; g[j + 2] = 0u;
  }
}

__global__ void prep_w(const float* __restrict__ w) {
  int i = blockIdx.x * 256 + threadIdx.x;      // covers 589824
  __half hv = __float2half_rn(w[i]);
  int n = i / 2304;
  int r = i - n * 2304;
  int cin = r / 9;
  int t9 = r - cin * 9;
  int kp = t9 * 256 + cin;                     // k'
  int c = kp >> 4, kk = kp & 15;               // k16 chunk, k within
  int by = n >> 7, c7 = n & 127;
  int wc = c7 >> 6, mi = (c7 >> 4) & 3, row16 = c7 & 15;
  int g = row16 & 7, rlo = row16 >> 3;
  int reg = (kk >> 3) * 2 + rlo;               // a0..a3
  int tg = (kk & 7) >> 1, hf = kk & 1;
  int lane = g * 4 + tg;
  wG[(size_t)c * 4096 + by * 2048 + wc * 1024 + mi * 256 + lane * 8 + reg * 2 + hf]
      = hv;
}

// ---- main ----
__global__ __launch_bounds__(256, 2)
void conv_main(float* __restrict__ out) {
  extern __shared__ char dsm[];
  const uint32_t sb = smem_u32(dsm);
  const int tid = threadIdx.x, lane = tid & 31, warp = tid >> 5;
  const int wc = warp & 1;                     // cout half (64) within CTA
  const int wmq = warp >> 1;                   // m quarter (32)
  const int n0 = blockIdx.x * 128;             // cout half of 256 (fast grid dim)
  const int by = blockIdx.x;
  const int m0 = blockIdx.y * 128;
  const int bimg = m0 >> 10;
  const int oh0 = (m0 >> 5) & 31;              // 4 output rows per tile

  float acc[4][4][4];
#pragma unroll
  for (int mi = 0; mi < 4; ++mi)
#pragma unroll
    for (int ni = 0; ni < 4; ++ni)
#pragma unroll
      for (int q = 0; q < 4; ++q) acc[mi][ni][q] = 0.f;

  // ldmatrix address components (thread-invariant)
  const int quad = lane >> 3;
  const int rowb = (quad & 1) * 8 + (lane & 7);          // k within 16
  const int ncolb = wmq * 32 + (quad >> 1) * 8;          // m column base
  const __half* xR = xH + ((size_t)(bimg * 256) * 65 + 2 * oh0) * 96;
  // W fragment stream base for this thread
  const char* wgp = (const char*)wG + by * 4096 + wc * 2048 + lane * 16;

  auto load_stage = [&](int s, int slot) {
    const int tap = s >> 3;                    // 8 stages per (kh,kw) tap
    const int cinb = (s & 7) << 5;
    const int kh = tap / 3, kw = tap - 3 * kh;
    const __half* xb = xR + (size_t)(cinb * 65 + kh) * 96 + kw * 32;
    const uint32_t xd = sb + slot * X_STAGE_B;
    // X: 512 x 16B chunks / 256 threads = 2 each; c: k=c>>4, ohl=(c>>2)&3, sg=c&3
#pragma unroll
    for (int jj = 0; jj < 2; ++jj) {
      const int c = tid + 256 * jj;
      const int k = c >> 4, ohl = (c >> 2) & 3, sg = c & 3;
      cpa16(xd + k * XROW + ohl * 64 + sg * 16,
            xb + (size_t)k * 6240 + ohl * 192 + sg * 8);
    }
    asm volatile("cp.async.commit_group;\n");
  };

  auto ldgW = [&](uint32_t (*dst)[4], int c) {
    const char* p = wgp + (size_t)c * 8192;
#pragma unroll
    for (int mi = 0; mi < 4; ++mi)
      ldg128nc(dst[mi], p + mi * 512);
  };

  load_stage(0, 0);
  load_stage(1, 1);
  load_stage(2, 2);
  load_stage(3, 3);

  uint32_t abuf[2][4][4];
  ldgW(abuf[0], 0);                            // chunk 0 prefetch

  int slot = 0;                                // s % 5
  int slotw = 4;                               // (s+4) % 5
  for (int s = 0; s < NIT; ++s) {
    asm volatile("cp.async.wait_group 3;\n" ::: "memory");
    __syncthreads();
    if (s + 4 < NIT) load_stage(s + 4, slotw);

    const uint32_t xbase = sb + slot * X_STAGE_B + rowb * XROW + ncolb * 2;
    // All 4 ldsm of this stage issued back-to-back: one latency exposure.
    uint32_t bx[4][4];
    ldsm4t(bx[0], xbase);                      // chunk0, ni 0,1
    ldsm4t(bx[1], xbase + 32);                 // chunk0, ni 2,3
    ldsm4t(bx[2], xbase + 16 * XROW);          // chunk1, ni 0,1
    ldsm4t(bx[3], xbase + 16 * XROW + 32);     // chunk1, ni 2,3
#pragma unroll
    for (int j = 0; j < 2; ++j) {              // two k16 chunks; c = 2s+j
      const int c = 2 * s + j;
      const int cn = (c + 1 < 144) ? c + 1 : c;
      ldgW(abuf[(j + 1) & 1], cn);             // prefetch next chunk's A-frags
      const uint32_t (*aw)[4] = abuf[j & 1];
#pragma unroll
      for (int ni = 0; ni < 4; ++ni) {
        const uint32_t b0 = bx[j * 2 + (ni >> 1)][(ni & 1) * 2];
        const uint32_t b1 = bx[j * 2 + (ni >> 1)][(ni & 1) * 2 + 1];
#pragma unroll
        for (int mi = 0; mi < 4; ++mi)
          mma16(acc[mi][ni], aw[mi], b0, b1);
      }
    }
    slot = (slot == NSTAGE - 1) ? 0 : slot + 1;
    slotw = (slotw == NSTAGE - 1) ? 0 : slotw + 1;
  }

  // Epilogue: D[cout][m]; m contiguous in out -> STG.64 pairs
  const int l4 = lane >> 2, lm = lane & 3;
  const int spb = m0 & 1023;
#pragma unroll
  for (int mi = 0; mi < 4; ++mi) {
    const int cr = n0 + wc * 64 + mi * 16 + l4;
#pragma unroll
    for (int ni = 0; ni < 4; ++ni) {
      const int mcol = wmq * 32 + ni * 8 + 2 * lm;
      float* o = out + ((size_t)(bimg * 256 + cr)) * 1024 + spb + mcol;
      *(float2*)o = make_float2(acc[mi][ni][0], acc[mi][ni][1]);
      *(float2*)(o + 8 * 1024) = make_float2(acc[mi][ni][2], acc[mi][ni][3]);
    }
  }
}

extern "C" void kernel_launch(void* const* d_in, const int* in_sizes, int n_in,
                              void* d_out, int out_size) {
  (void)out_size;
  const float* x = (const float*)d_in[0];
  const float* w = (const float*)d_in[1];
  if (n_in >= 2 && in_sizes[0] < in_sizes[1]) {  // defensive ordering by size
    x = (const float*)d_in[1];
    w = (const float*)d_in[0];
  }
  cudaFuncSetAttribute(conv_main, cudaFuncAttributeMaxDynamicSharedMemorySize,
                       SMEM_BYTES);
  prep_x<<<32768, 256>>>((const float4*)x);
  prep_w<<<2304, 256>>>(w);
  dim3 grid(2, 256);                           // cout-half fastest: L2 X sharing
  conv_main<<<grid, 256, SMEM_BYTES>>>((float*)d_out);
}

// round 15
// speedup vs baseline: 1.0856x; 1.0856x over previous
#include <cuda_runtime.h>
#include <cuda_fp16.h>
#include <cstdint>
#include <cstddef>

// Conv 3x3 s2 p1: x[32,256,64,64] * w[256,256,3,3] -> out[32,256,32,32]
// (crop mask is all-ones: python slice clamping empties every zero segment).
// Implicit GEMM, swapped operands: D[cout][m] = W[cout][k] * X[k][m],
// K re-enumerated k'=(kh*3+kw)*256+cin. FP16 datapath, fp32 accumulate.
// W streams from L1/L2 via ld.global.nc.v4 into a register double-buffer;
// smem carries X only (4-stage cp.async pipeline). Tile 128x128x32, 8 warps
// (64cx32m), 2 CTAs/SM, cout-pairs adjacent in grid for L2 X sharing.
// This round: prep_x + prep_w fused into ONE launch (block-range split);
// conv_main reverted to the best-known R13 configuration.

namespace {
constexpr int NIT = 72;                        // 2304 / 32
constexpr int XROW = 272;                      // bytes per k-row (256 data + 16 pad)
constexpr int X_STAGE_B = 32 * XROW;           // 8704
constexpr int SMEM_BYTES = 4 * X_STAGE_B;      // 34816 (x2 CTAs = 70KB/SM)
constexpr int PREPX_BLOCKS = 32768;            // 8388608 float4s / 256
constexpr int PREPW_BLOCKS = 2304;             // 589824 / 256
}

// xH[b][cin][ihp(65)][kw(3)][32] halves: pre-shifted, parity-deinterleaved,
// fp16-rounded rows; ihp=0 is an all-zero guard row (ih=-1).
__device__ __half xH[51118080];
// wG: A-fragment stream for direct LDG, 8KB per k16 chunk c (144 chunks):
// halfidx = c*4096 + by*2048 + wc*1024 + mi*256 + lane*8 + reg*2 + hf
__device__ __half wG[589824];

__device__ __forceinline__ uint32_t smem_u32(const void* p) {
  uint32_t a;
  asm("{ .reg .u64 t; cvta.to.shared.u64 t, %1; cvt.u32.u64 %0, t; }" : "=r"(a) : "l"(p));
  return a;
}
__device__ __forceinline__ void ldg128nc(uint32_t* r, const void* p) {
  asm("ld.global.nc.v4.b32 {%0,%1,%2,%3}, [%4];"
      : "=r"(r[0]), "=r"(r[1]), "=r"(r[2]), "=r"(r[3]) : "l"(p));
}
__device__ __forceinline__ void ldsm4t(uint32_t* r, uint32_t a) {
  asm volatile("ldmatrix.sync.aligned.m8n8.x4.trans.shared.b16 {%0,%1,%2,%3}, [%4];"
               : "=r"(r[0]), "=r"(r[1]), "=r"(r[2]), "=r"(r[3]) : "r"(a));
}
__device__ __forceinline__ void cpa16(uint32_t dst, const void* src) {
  asm volatile("cp.async.cg.shared.global [%0], [%1], 16;\n" :: "r"(dst), "l"(src));
}
__device__ __forceinline__ void mma16(float* c, const uint32_t* a, uint32_t b0, uint32_t b1) {
  asm volatile(
      "mma.sync.aligned.m16n8k16.row.col.f32.f16.f16.f32 "
      "{%0,%1,%2,%3}, {%4,%5,%6,%7}, {%8,%9}, {%0,%1,%2,%3};"
      : "+f"(c[0]), "+f"(c[1]), "+f"(c[2]), "+f"(c[3])
      : "r"(a[0]), "r"(a[1]), "r"(a[2]), "r"(a[3]), "r"(b0), "r"(b1));
}

// ---- fused prepass: blocks [0, PREPX_BLOCKS) do X, the rest do W ----
__global__ void prep_fused(const float4* __restrict__ x4,
                           const float* __restrict__ w) {
  if (blockIdx.x < PREPX_BLOCKS) {
    int i = blockIdx.x * 256 + threadIdx.x;    // covers 8388608 float4s
    float4 v = x4[i];
    __half h0 = __float2half_rn(v.x), h1 = __float2half_rn(v.y);
    __half h2 = __float2half_rn(v.z), h3 = __float2half_rn(v.w);
    int e = i << 2;
    int iw0 = e & 63;                          // 0,4,...,60
    int rid = e >> 6;                          // (b*256+cin)*64 + ih
    int bc = rid >> 6, ih = rid & 63;
    __half* base = xH + (size_t)(bc * 65 + ih + 1) * 96;
    int q = iw0 >> 1;                          // even
    // kw=1 plane: even iw; kw=2 plane: odd iw (q even -> 4B aligned)
    *(__half2*)(base + 32 + q) = __halves2half2(h0, h2);
    *(__half2*)(base + 64 + q) = __halves2half2(h1, h3);
    // kw=0 plane: [0, odd shifted right]
    base[q + 1] = h1;
    if (iw0 < 60) base[q + 2] = h3;
    if (iw0 == 0) base[0] = __float2half_rn(0.f);
    // fused guard-row zeroing (ihp=0): ih==0 threads cover 48 u32 per (b,cin)
    if (ih == 0) {
      uint32_t* g = (uint32_t*)(base - 96);    // guard row, 96 halves = 48 u32
      int j = (iw0 >> 2) * 3;                  // 16 threads x 3 u32 = 48
      g[j] = 0u; g[j + 1] = 0u; g[j + 2] = 0u;
    }
  } else {
    int i = (blockIdx.x - PREPX_BLOCKS) * 256 + threadIdx.x;  // covers 589824
    __half hv = __float2half_rn(w[i]);
    int n = i / 2304;
    int r = i - n * 2304;
    int cin = r / 9;
    int t9 = r - cin * 9;
    int kp = t9 * 256 + cin;                   // k'
    int c = kp >> 4, kk = kp & 15;             // k16 chunk, k within
    int by = n >> 7, c7 = n & 127;
    int wc = c7 >> 6, mi = (c7 >> 4) & 3, row16 = c7 & 15;
    int g = row16 & 7, rlo = row16 >> 3;
    int reg = (kk >> 3) * 2 + rlo;             // a0..a3
    int tg = (kk & 7) >> 1, hf = kk & 1;
    int lane = g * 4 + tg;
    wG[(size_t)c * 4096 + by * 2048 + wc * 1024 + mi * 256 + lane * 8 + reg * 2 + hf]
        = hv;
  }
}

// ---- main ----
__global__ __launch_bounds__(256, 2)
void conv_main(float* __restrict__ out) {
  extern __shared__ char dsm[];
  const uint32_t sb = smem_u32(dsm);
  const int tid = threadIdx.x, lane = tid & 31, warp = tid >> 5;
  const int wc = warp & 1;                     // cout half (64) within CTA
  const int wmq = warp >> 1;                   // m quarter (32)
  const int n0 = blockIdx.x * 128;             // cout half of 256 (fast grid dim)
  const int by = blockIdx.x;
  const int m0 = blockIdx.y * 128;
  const int bimg = m0 >> 10;
  const int oh0 = (m0 >> 5) & 31;              // 4 output rows per tile

  float acc[4][4][4];
#pragma unroll
  for (int mi = 0; mi < 4; ++mi)
#pragma unroll
    for (int ni = 0; ni < 4; ++ni)
#pragma unroll
      for (int q = 0; q < 4; ++q) acc[mi][ni][q] = 0.f;

  // ldmatrix address components (thread-invariant)
  const int quad = lane >> 3;
  const int rowb = (quad & 1) * 8 + (lane & 7);          // k within 16
  const int ncolb = wmq * 32 + (quad >> 1) * 8;          // m column base
  const __half* xR = xH + ((size_t)(bimg * 256) * 65 + 2 * oh0) * 96;
  // W fragment stream base for this thread
  const char* wgp = (const char*)wG + by * 4096 + wc * 2048 + lane * 16;

  auto load_stage = [&](int s, int slot) {
    const int tap = s >> 3;                    // 8 stages per (kh,kw) tap
    const int cinb = (s & 7) << 5;
    const int kh = tap / 3, kw = tap - 3 * kh;
    const __half* xb = xR + (size_t)(cinb * 65 + kh) * 96 + kw * 32;
    const uint32_t xd = sb + slot * X_STAGE_B;
    // X: 512 x 16B chunks / 256 threads = 2 each; c: k=c>>4, ohl=(c>>2)&3, sg=c&3
#pragma unroll
    for (int jj = 0; jj < 2; ++jj) {
      const int c = tid + 256 * jj;
      const int k = c >> 4, ohl = (c >> 2) & 3, sg = c & 3;
      cpa16(xd + k * XROW + ohl * 64 + sg * 16,
            xb + (size_t)k * 6240 + ohl * 192 + sg * 8);
    }
    asm volatile("cp.async.commit_group;\n");
  };

  auto ldgW = [&](uint32_t (*dst)[4], int c) {
    const char* p = wgp + (size_t)c * 8192;
#pragma unroll
    for (int mi = 0; mi < 4; ++mi)
      ldg128nc(dst[mi], p + mi * 512);
  };

  load_stage(0, 0);
  load_stage(1, 1);
  load_stage(2, 2);

  uint32_t abuf[2][4][4];
  ldgW(abuf[0], 0);                            // chunk 0 prefetch

  for (int s = 0; s < NIT; ++s) {
    const int buf = s & 3;
    asm volatile("cp.async.wait_group 2;\n" ::: "memory");
    __syncthreads();
    if (s + 3 < NIT) load_stage(s + 3, (s + 3) & 3);

    const uint32_t xbase = sb + buf * X_STAGE_B + rowb * XROW + ncolb * 2;
#pragma unroll
    for (int j = 0; j < 2; ++j) {              // two k16 chunks; c = 2s+j
      const int c = 2 * s + j;
      const int cn = (c + 1 < 144) ? c + 1 : c;
      ldgW(abuf[(j + 1) & 1], cn);             // prefetch next chunk's A-frags
      uint32_t bx[2][4];
      const uint32_t xj = xbase + j * 16 * XROW;
      ldsm4t(bx[0], xj);                       // ni 0,1
      ldsm4t(bx[1], xj + 32);                  // ni 2,3 (m +16 halves)
      const uint32_t (*aw)[4] = abuf[j & 1];
#pragma unroll
      for (int ni = 0; ni < 4; ++ni) {
        const uint32_t b0 = bx[ni >> 1][(ni & 1) * 2];
        const uint32_t b1 = bx[ni >> 1][(ni & 1) * 2 + 1];
#pragma unroll
        for (int mi = 0; mi < 4; ++mi)
          mma16(acc[mi][ni], aw[mi], b0, b1);
      }
    }
  }

  // Epilogue: D[cout][m]; m contiguous in out -> STG.64 pairs
  const int l4 = lane >> 2, lm = lane & 3;
  const int spb = m0 & 1023;
#pragma unroll
  for (int mi = 0; mi < 4; ++mi) {
    const int cr = n0 + wc * 64 + mi * 16 + l4;
#pragma unroll
    for (int ni = 0; ni < 4; ++ni) {
      const int mcol = wmq * 32 + ni * 8 + 2 * lm;
      float* o = out + ((size_t)(bimg * 256 + cr)) * 1024 + spb + mcol;
      *(float2*)o = make_float2(acc[mi][ni][0], acc[mi][ni][1]);
      *(float2*)(o + 8 * 1024) = make_float2(acc[mi][ni][2], acc[mi][ni][3]);
    }
  }
}

extern "C" void kernel_launch(void* const* d_in, const int* in_sizes, int n_in,
                              void* d_out, int out_size) {
  (void)out_size;
  const float* x = (const float*)d_in[0];
  const float* w = (const float*)d_in[1];
  if (n_in >= 2 && in_sizes[0] < in_sizes[1]) {  // defensive ordering by size
    x = (const float*)d_in[1];
    w = (const float*)d_in[0];
  }
  cudaFuncSetAttribute(conv_main, cudaFuncAttributeMaxDynamicSharedMemorySize,
                       SMEM_BYTES);
  prep_fused<<<PREPX_BLOCKS + PREPW_BLOCKS, 256>>>((const float4*)x, w);
  dim3 grid(2, 256);                           // cout-half fastest: L2 X sharing
  conv_main<<<grid, 256, SMEM_BYTES>>>((float*)d_out);
}

// round 16
// speedup vs baseline: 1.2409x; 1.1431x over previous
#include <cuda_runtime.h>
#include <cuda_fp16.h>
#include <cstdint>
#include <cstddef>

// Conv 3x3 s2 p1: x[32,256,64,64] * w[256,256,3,3] -> out[32,256,32,32]
// (crop mask is all-ones: python slice clamping empties every zero segment).
// Implicit GEMM, swapped operands: D[cout][m] = W[cout][k] * X[k][m].
// FP16 datapath, fp32 accumulate. W streams from L1/L2 (ld.global.nc.v4,
// register double-buffer). THIS ROUND: fully warp-autonomous pipelines --
// each warp owns a private 4-slot X ring (its own 32-m segment, duplicated
// across the wc-pair), cp.async + wait_group + __syncwarp only; ZERO
// __syncthreads in the mainloop, so 16 warps/SM drift freely and cover each
// other's latency. Tile 128x128x32, 2 CTAs/SM, cout-pairs adjacent in grid.

namespace {
constexpr int NIT = 72;                        // 2304 / 32
constexpr int WXROW = 80;                      // bytes per k-row per warp (64+16 pad)
constexpr int WX_STAGE = 32 * WXROW;           // 2560 B per warp per stage
constexpr int NSTAGE = 4;
constexpr int WARP_SMEM = NSTAGE * WX_STAGE;   // 10240 B per warp
constexpr int SMEM_BYTES = 8 * WARP_SMEM;      // 81920 (x2 CTAs = 160KB/SM)
constexpr int PREPX_BLOCKS = 32768;            // 8388608 float4s / 256
constexpr int PREPW_BLOCKS = 2304;             // 589824 / 256
}

// xH[b][cin][ihp(65)][kw(3)][32] halves: pre-shifted, parity-deinterleaved,
// fp16-rounded rows; ihp=0 is an all-zero guard row (ih=-1).
__device__ __half xH[51118080];
// wG: A-fragment stream for direct LDG, 8KB per k16 chunk c (144 chunks):
// halfidx = c*4096 + by*2048 + wc*1024 + mi*256 + lane*8 + reg*2 + hf
__device__ __half wG[589824];

__device__ __forceinline__ uint32_t smem_u32(const void* p) {
  uint32_t a;
  asm("{ .reg .u64 t; cvta.to.shared.u64 t, %1; cvt.u32.u64 %0, t; }" : "=r"(a) : "l"(p));
  return a;
}
__device__ __forceinline__ void ldg128nc(uint32_t* r, const void* p) {
  asm("ld.global.nc.v4.b32 {%0,%1,%2,%3}, [%4];"
      : "=r"(r[0]), "=r"(r[1]), "=r"(r[2]), "=r"(r[3]) : "l"(p));
}
__device__ __forceinline__ void ldsm4t(uint32_t* r, uint32_t a) {
  asm volatile("ldmatrix.sync.aligned.m8n8.x4.trans.shared.b16 {%0,%1,%2,%3}, [%4];"
               : "=r"(r[0]), "=r"(r[1]), "=r"(r[2]), "=r"(r[3]) : "r"(a));
}
__device__ __forceinline__ void cpa16(uint32_t dst, const void* src) {
  asm volatile("cp.async.cg.shared.global [%0], [%1], 16;\n" :: "r"(dst), "l"(src));
}
__device__ __forceinline__ void mma16(float* c, const uint32_t* a, uint32_t b0, uint32_t b1) {
  asm volatile(
      "mma.sync.aligned.m16n8k16.row.col.f32.f16.f16.f32 "
      "{%0,%1,%2,%3}, {%4,%5,%6,%7}, {%8,%9}, {%0,%1,%2,%3};"
      : "+f"(c[0]), "+f"(c[1]), "+f"(c[2]), "+f"(c[3])
      : "r"(a[0]), "r"(a[1]), "r"(a[2]), "r"(a[3]), "r"(b0), "r"(b1));
}

// ---- fused prepass: blocks [0, PREPX_BLOCKS) do X, the rest do W ----
__global__ void prep_fused(const float4* __restrict__ x4,
                           const float* __restrict__ w) {
  if (blockIdx.x < PREPX_BLOCKS) {
    int i = blockIdx.x * 256 + threadIdx.x;    // covers 8388608 float4s
    float4 v = x4[i];
    __half h0 = __float2half_rn(v.x), h1 = __float2half_rn(v.y);
    __half h2 = __float2half_rn(v.z), h3 = __float2half_rn(v.w);
    int e = i << 2;
    int iw0 = e & 63;                          // 0,4,...,60
    int rid = e >> 6;                          // (b*256+cin)*64 + ih
    int bc = rid >> 6, ih = rid & 63;
    __half* base = xH + (size_t)(bc * 65 + ih + 1) * 96;
    int q = iw0 >> 1;                          // even
    // kw=1 plane: even iw; kw=2 plane: odd iw (q even -> 4B aligned)
    *(__half2*)(base + 32 + q) = __halves2half2(h0, h2);
    *(__half2*)(base + 64 + q) = __halves2half2(h1, h3);
    // kw=0 plane: [0, odd shifted right]
    base[q + 1] = h1;
    if (iw0 < 60) base[q + 2] = h3;
    if (iw0 == 0) base[0] = __float2half_rn(0.f);
    // fused guard-row zeroing (ihp=0): ih==0 threads cover 48 u32 per (b,cin)
    if (ih == 0) {
      uint32_t* g = (uint32_t*)(base - 96);    // guard row, 96 halves = 48 u32
      int j = (iw0 >> 2) * 3;                  // 16 threads x 3 u32 = 48
      g[j] = 0u; g[j + 1] = 0u; g[j + 2] = 0u;
    }
  } else {
    int i = (blockIdx.x - PREPX_BLOCKS) * 256 + threadIdx.x;  // covers 589824
    __half hv = __float2half_rn(w[i]);
    int n = i / 2304;
    int r = i - n * 2304;
    int cin = r / 9;
    int t9 = r - cin * 9;
    int kp = t9 * 256 + cin;                   // k'
    int c = kp >> 4, kk = kp & 15;             // k16 chunk, k within
    int by = n >> 7, c7 = n & 127;
    int wc = c7 >> 6, mi = (c7 >> 4) & 3, row16 = c7 & 15;
    int g = row16 & 7, rlo = row16 >> 3;
    int reg = (kk >> 3) * 2 + rlo;             // a0..a3
    int tg = (kk & 7) >> 1, hf = kk & 1;
    int lane = g * 4 + tg;
    wG[(size_t)c * 4096 + by * 2048 + wc * 1024 + mi * 256 + lane * 8 + reg * 2 + hf]
        = hv;
  }
}

// ---- main ----
__global__ __launch_bounds__(256, 2)
void conv_main(float* __restrict__ out) {
  extern __shared__ char dsm[];
  const uint32_t sb = smem_u32(dsm);
  const int tid = threadIdx.x, lane = tid & 31, warp = tid >> 5;
  const int wc = warp & 1;                     // cout half (64) within CTA
  const int wmq = warp >> 1;                   // m quarter (32) == oh row index
  const int n0 = blockIdx.x * 128;             // cout half of 256 (fast grid dim)
  const int by = blockIdx.x;
  const int m0 = blockIdx.y * 128;
  const int bimg = m0 >> 10;
  const int oh0 = (m0 >> 5) & 31;              // 4 output rows per tile

  float acc[4][4][4];
#pragma unroll
  for (int mi = 0; mi < 4; ++mi)
#pragma unroll
    for (int ni = 0; ni < 4; ++ni)
#pragma unroll
      for (int q = 0; q < 4; ++q) acc[mi][ni][q] = 0.f;

  // ldmatrix address components (warp-local X ring)
  const int quad = lane >> 3;
  const int rowb = (quad & 1) * 8 + (lane & 7);          // k within 16
  const uint32_t colb = (quad >> 1) * 16;                // m byte offset in seg
  const uint32_t wbase = sb + warp * WARP_SMEM;
  const __half* xR = xH + ((size_t)(bimg * 256) * 65 + 2 * oh0) * 96;
  // W fragment stream base for this thread
  const char* wgp = (const char*)wG + by * 4096 + wc * 2048 + lane * 16;

  // Producer: warp loads its OWN 32-m segment (oh row = wmq), 2KB/stage,
  // 4x 16B chunks per lane: c = lane + 32*j -> k = c>>2, sg = c&3.
  auto load_stage = [&](int s, int slot) {
    const int tap = s >> 3;                    // 8 stages per (kh,kw) tap
    const int cinb = (s & 7) << 5;
    const int kh = tap / 3, kw = tap - 3 * kh;
    const __half* xb = xR + (size_t)(cinb * 65 + kh) * 96 + kw * 32 + wmq * 192;
    const uint32_t xd = wbase + slot * WX_STAGE;
#pragma unroll
    for (int j = 0; j < 4; ++j) {
      const int c = lane + 32 * j;
      const int k = c >> 2, sg = c & 3;
      cpa16(xd + k * WXROW + sg * 16, xb + (size_t)k * 6240 + sg * 8);
    }
    asm volatile("cp.async.commit_group;\n");
  };

  auto ldgW = [&](uint32_t (*dst)[4], int c) {
    const char* p = wgp + (size_t)c * 8192;
#pragma unroll
    for (int mi = 0; mi < 4; ++mi)
      ldg128nc(dst[mi], p + mi * 512);
  };

  load_stage(0, 0);
  load_stage(1, 1);
  load_stage(2, 2);

  uint32_t abuf[2][4][4];
  ldgW(abuf[0], 0);                            // chunk 0 prefetch

  for (int s = 0; s < NIT; ++s) {
    const int slot = s & 3;
    asm volatile("cp.async.wait_group 2;\n" ::: "memory");
    __syncwarp();                              // sibling lanes' copies visible
    if (s + 3 < NIT) load_stage(s + 3, (s + 3) & 3);

    const uint32_t xbase = wbase + slot * WX_STAGE + rowb * WXROW + colb;
#pragma unroll
    for (int j = 0; j < 2; ++j) {              // two k16 chunks; c = 2s+j
      const int c = 2 * s + j;
      const int cn = (c + 1 < 144) ? c + 1 : c;
      ldgW(abuf[(j + 1) & 1], cn);             // prefetch next chunk's A-frags
      uint32_t bx[2][4];
      const uint32_t xj = xbase + j * 16 * WXROW;
      ldsm4t(bx[0], xj);                       // m [0,16) of segment: ni 0,1
      ldsm4t(bx[1], xj + 32);                  // m [16,32): ni 2,3
      const uint32_t (*aw)[4] = abuf[j & 1];
#pragma unroll
      for (int ni = 0; ni < 4; ++ni) {
        const uint32_t b0 = bx[ni >> 1][(ni & 1) * 2];
        const uint32_t b1 = bx[ni >> 1][(ni & 1) * 2 + 1];
#pragma unroll
        for (int mi = 0; mi < 4; ++mi)
          mma16(acc[mi][ni], aw[mi], b0, b1);
      }
    }
  }

  // Epilogue: D[cout][m]; m contiguous in out -> STG.64 pairs
  const int l4 = lane >> 2, lm = lane & 3;
  const int spb = m0 & 1023;
#pragma unroll
  for (int mi = 0; mi < 4; ++mi) {
    const int cr = n0 + wc * 64 + mi * 16 + l4;
#pragma unroll
    for (int ni = 0; ni < 4; ++ni) {
      const int mcol = wmq * 32 + ni * 8 + 2 * lm;
      float* o = out + ((size_t)(bimg * 256 + cr)) * 1024 + spb + mcol;
      *(float2*)o = make_float2(acc[mi][ni][0], acc[mi][ni][1]);
      *(float2*)(o + 8 * 1024) = make_float2(acc[mi][ni][2], acc[mi][ni][3]);
    }
  }
}

extern "C" void kernel_launch(void* const* d_in, const int* in_sizes, int n_in,
                              void* d_out, int out_size) {
  (void)out_size;
  const float* x = (const float*)d_in[0];
  const float* w = (const float*)d_in[1];
  if (n_in >= 2 && in_sizes[0] < in_sizes[1]) {  // defensive ordering by size
    x = (const float*)d_in[1];
    w = (const float*)d_in[0];
  }
  cudaFuncSetAttribute(conv_main, cudaFuncAttributeMaxDynamicSharedMemorySize,
                       SMEM_BYTES);
  prep_fused<<<PREPX_BLOCKS + PREPW_BLOCKS, 256>>>((const float4*)x, w);
  dim3 grid(2, 256);                           // cout-half fastest: L2 X sharing
  conv_main<<<grid, 256, SMEM_BYTES>>>((float*)d_out);
}